// round 4
// baseline (speedup 1.0000x reference)
#include <cuda_runtime.h>

// SE(3) exp(xi) @ poses_init, 4 poses per thread, split-grid pairing
// (i_j = t + j*H) so every LDG/STG is unit-stride coalesced. All loads
// front-batched for max MLP; branchless Rodrigues (no normalization).
#define EPS_THETA 1e-6f
#define UNROLL 4

__device__ __forceinline__ float4 f4_fma(float a, float4 x, float4 acc) {
    acc.x = fmaf(a, x.x, acc.x);
    acc.y = fmaf(a, x.y, acc.y);
    acc.z = fmaf(a, x.z, acc.z);
    acc.w = fmaf(a, x.w, acc.w);
    return acc;
}
__device__ __forceinline__ float4 f4_scale(float a, float4 x) {
    return make_float4(a * x.x, a * x.y, a * x.z, a * x.w);
}

__global__ void __launch_bounds__(256) se3_compose4_kernel(
    const float*  __restrict__ xi,      // [N, 6]
    const float4* __restrict__ poses,   // [N, 4] rows of float4
    float4*       __restrict__ out,     // [N, 4] rows of float4
    int H, int n)
{
    int t = blockIdx.x * blockDim.x + threadIdx.x;
    if (t >= H) return;

    int   idx[UNROLL];
    bool  has[UNROLL];
#pragma unroll
    for (int j = 0; j < UNROLL; j++) {
        idx[j] = t + j * H;
        has[j] = (idx[j] < n);
    }

    // ---- front-batch ALL loads ----
    float2 x0[UNROLL], x1[UNROLL], x2[UNROLL];
#pragma unroll
    for (int j = 0; j < UNROLL; j++) {
        if (has[j]) {
            const float2* xp = reinterpret_cast<const float2*>(xi + (size_t)idx[j] * 6);
            x0[j] = __ldcs(xp + 0);
            x1[j] = __ldcs(xp + 1);
            x2[j] = __ldcs(xp + 2);
        }
    }

    float4 p0[UNROLL], p1[UNROLL], p2[UNROLL], p3[UNROLL];
#pragma unroll
    for (int j = 0; j < UNROLL; j++) {
        if (has[j]) {
            const float4* P = poses + (size_t)idx[j] * 4;
            p0[j] = __ldcs(P + 0);
            p1[j] = __ldcs(P + 1);
            p2[j] = __ldcs(P + 2);
            p3[j] = __ldcs(P + 3);
        }
    }

    // ---- compute + store per pose ----
#pragma unroll
    for (int j = 0; j < UNROLL; j++) {
        if (!has[j]) continue;
        float tx = x0[j].x, ty = x0[j].y, tz = x1[j].x;
        float wx = x1[j].y, wy = x2[j].x, wz = x2[j].y;

        float theta2 = wx*wx + wy*wy + wz*wz;
        float theta  = sqrtf(theta2);
        bool  small  = theta < EPS_THETA;
        // R = I + A*W + B*W^2, W = skew(omega), W^2 = w w^T - theta^2 I
        // small: A=1, B=0 (matches reference R_small = I + skew(omega))
        float inv_t2 = 1.0f / theta2;
        float A = small ? 1.0f : sinf(theta) / theta;
        float B = small ? 0.0f : (1.0f - cosf(theta)) * inv_t2;

        float R00 = 1.0f + B * (wx*wx - theta2);
        float R11 = 1.0f + B * (wy*wy - theta2);
        float R22 = 1.0f + B * (wz*wz - theta2);
        float bxy = B*wx*wy, bxz = B*wx*wz, byz = B*wy*wz;
        float awx = A*wx, awy = A*wy, awz = A*wz;
        float R01 = bxy - awz, R02 = bxz + awy;
        float R10 = bxy + awz, R12 = byz - awx;
        float R20 = bxz - awy, R21 = byz + awx;

        float4 o0 = f4_scale(R00, p0[j]);
        o0 = f4_fma(R01, p1[j], o0); o0 = f4_fma(R02, p2[j], o0); o0 = f4_fma(tx, p3[j], o0);
        float4 o1 = f4_scale(R10, p0[j]);
        o1 = f4_fma(R11, p1[j], o1); o1 = f4_fma(R12, p2[j], o1); o1 = f4_fma(ty, p3[j], o1);
        float4 o2 = f4_scale(R20, p0[j]);
        o2 = f4_fma(R21, p1[j], o2); o2 = f4_fma(R22, p2[j], o2); o2 = f4_fma(tz, p3[j], o2);

        float4* O = out + (size_t)idx[j] * 4;
        __stcs(O + 0, o0);
        __stcs(O + 1, o1);
        __stcs(O + 2, o2);
        __stcs(O + 3, p3[j]);
    }
}

extern "C" void kernel_launch(void* const* d_in, const int* in_sizes, int n_in,
                              void* d_out, int out_size) {
    const float*  xi    = (const float*)d_in[0];   // [N,6]
    const float4* poses = (const float4*)d_in[1];  // [N,4,4] as rows of float4
    float4*       out   = (float4*)d_out;
    int n = in_sizes[0] / 6;
    int H = (n + UNROLL - 1) / UNROLL;
    int threads = 256;
    int blocks = (H + threads - 1) / threads;
    se3_compose4_kernel<<<blocks, threads>>>(xi, poses, out, H, n);
}